// round 4
// baseline (speedup 1.0000x reference)
#include <cuda_runtime.h>
#include <cuda_bf16.h>

// ---------------------------------------------------------------------------
// EventTokenizer: T=262144 frames, D_IN=512, K=64 contiguous segments.
// Dominated by one 512MB streaming reduction (features -> per-segment sums).
// ---------------------------------------------------------------------------

#define TFRAMES   262144
#define KSEG      64
#define DIN       512
#define DMODEL    256
#define TYPEEMB   32
#define ZDIM      552      // 512 + 8 + 32
#define EPSF      1e-6f
#define CONF_TH   0.3f

// Output layout (float32, concatenated in reference return order):
// tokens [64*256] | mask [64] | type [64] | conf [64] | s_k [64*8]
#define OUT_TOKENS 0
#define OUT_MASK   16384
#define OUT_TYPE   16448
#define OUT_CONF   16512
#define OUT_SK     16576

// ----- scratch (device globals; no allocation allowed) -----
__device__ float g_esum[KSEG * DIN];   // per-segment feature sums
__device__ float g_sumE[KSEG];
__device__ int   g_maxE[KSEG];         // float bits (energy >= 0)
__device__ float g_sumFC[KSEG];
__device__ float g_sumSC[KSEG * 3];
__device__ float g_ent[KSEG];          // sum p*log(p+eps)
__device__ float g_sk[KSEG * 8];

// ---------------------------------------------------------------------------
__global__ void k_zero() {
    int i = blockIdx.x * blockDim.x + threadIdx.x;
    if (i < KSEG * DIN) g_esum[i] = 0.f;
    if (i < KSEG) { g_sumE[i] = 0.f; g_maxE[i] = 0; g_sumFC[i] = 0.f; g_ent[i] = 0.f; }
    if (i < KSEG * 3) g_sumSC[i] = 0.f;
}

// ---------------------------------------------------------------------------
// Merged big pass.
//   blocks [0,1024): features. Each block owns 256 contiguous frames; thread t
//     owns float4 columns [4t,4t+4). FAST PATH when the whole chunk lies inside
//     one segment (all but <=63 blocks): branch-free loop, 8 independent
//     LDG.128 in flight per warp.
//   blocks [1024,1088): scalar reductions (energy sum/max, frame_conf,
//     stream_conf) with coalesced stride-by-thread walking.
__global__ void __launch_bounds__(128) k_main(const float4* __restrict__ feat,
                                              const int* __restrict__ segend,
                                              const float* __restrict__ energy,
                                              const float* __restrict__ fconf,
                                              const float* __restrict__ sconf) {
    __shared__ int send[KSEG];
    if (threadIdx.x < KSEG) send[threadIdx.x] = segend[threadIdx.x];
    __syncthreads();

    const int tid = threadIdx.x;

    if (blockIdx.x < 1024) {
        // ---------------- feature reduction ----------------
        const int f0 = blockIdx.x * 256;
        const int f1 = f0 + 256;
        int cur = 0;
        while (send[cur] <= f0) cur++;

        const float4* p = feat + (size_t)f0 * 128 + tid;

        if (send[cur] >= f1) {
            // fast path: entire chunk inside segment `cur`
            float4 a0 = make_float4(0.f, 0.f, 0.f, 0.f);
            float4 a1 = make_float4(0.f, 0.f, 0.f, 0.f);
            #pragma unroll 4
            for (int i = 0; i < 256; i += 2) {
                float4 v0 = __ldcs(p + (size_t)i * 128);
                float4 v1 = __ldcs(p + (size_t)(i + 1) * 128);
                a0.x += v0.x; a0.y += v0.y; a0.z += v0.z; a0.w += v0.w;
                a1.x += v1.x; a1.y += v1.y; a1.z += v1.z; a1.w += v1.w;
            }
            a0.x += a1.x; a0.y += a1.y; a0.z += a1.z; a0.w += a1.w;
            float* dst = &g_esum[cur * DIN + tid * 4];
            atomicAdd(dst + 0, a0.x); atomicAdd(dst + 1, a0.y);
            atomicAdd(dst + 2, a0.z); atomicAdd(dst + 3, a0.w);
        } else {
            // slow path: block straddles segment boundary(ies)
            float4 acc = make_float4(0.f, 0.f, 0.f, 0.f);
            for (int f = f0; f < f1; ++f, p += 128) {
                if (f >= send[cur]) {
                    float* dst = &g_esum[cur * DIN + tid * 4];
                    atomicAdd(dst + 0, acc.x); atomicAdd(dst + 1, acc.y);
                    atomicAdd(dst + 2, acc.z); atomicAdd(dst + 3, acc.w);
                    acc = make_float4(0.f, 0.f, 0.f, 0.f);
                    while (send[cur] <= f) cur++;
                }
                float4 v = __ldcs(p);
                acc.x += v.x; acc.y += v.y; acc.z += v.z; acc.w += v.w;
            }
            float* dst = &g_esum[cur * DIN + tid * 4];
            atomicAdd(dst + 0, acc.x); atomicAdd(dst + 1, acc.y);
            atomicAdd(dst + 2, acc.z); atomicAdd(dst + 3, acc.w);
        }
    } else {
        // ---------------- scalar reductions ----------------
        const int b = blockIdx.x - 1024;            // 64 blocks, 4096 frames each
        const int base = b * 4096 + tid;            // stride-128 stepping (coalesced)
        int cur = 0;
        while (send[cur] <= base) cur++;

        float sE = 0.f, mx = 0.f, aF = 0.f, s0 = 0.f, s1 = 0.f, s2 = 0.f;
        #pragma unroll 8
        for (int i = 0; i < 32; ++i) {
            int f = base + i * 128;
            if (f >= send[cur]) {
                atomicAdd(&g_sumE[cur], sE);
                atomicMax(&g_maxE[cur], __float_as_int(mx));
                atomicAdd(&g_sumFC[cur], aF);
                atomicAdd(&g_sumSC[cur * 3 + 0], s0);
                atomicAdd(&g_sumSC[cur * 3 + 1], s1);
                atomicAdd(&g_sumSC[cur * 3 + 2], s2);
                sE = mx = aF = s0 = s1 = s2 = 0.f;
                while (send[cur] <= f) cur++;
            }
            float e = energy[f];
            sE += e; mx = fmaxf(mx, e);
            aF += fconf[f];
            s0 += sconf[3 * f + 0]; s1 += sconf[3 * f + 1]; s2 += sconf[3 * f + 2];
        }
        atomicAdd(&g_sumE[cur], sE);
        atomicMax(&g_maxE[cur], __float_as_int(mx));
        atomicAdd(&g_sumFC[cur], aF);
        atomicAdd(&g_sumSC[cur * 3 + 0], s0);
        atomicAdd(&g_sumSC[cur * 3 + 1], s1);
        atomicAdd(&g_sumSC[cur * 3 + 2], s2);
    }
}

// ---------------------------------------------------------------------------
// Entropy pass (needs g_sumE): 256 blocks x 256 threads x 4 frames, coalesced,
// fixed unroll so loads batch. Warp-aggregated atomic on the final flush.
__global__ void __launch_bounds__(256) k_ent(const float* __restrict__ energy,
                                             const int* __restrict__ segend) {
    __shared__ int   send[KSEG];
    __shared__ float sinv[KSEG];
    if (threadIdx.x < KSEG) {
        send[threadIdx.x] = segend[threadIdx.x];
        sinv[threadIdx.x] = 1.f / (g_sumE[threadIdx.x] + EPSF);
    }
    __syncthreads();

    const int f0 = blockIdx.x * 1024 + threadIdx.x;
    int cur = 0;
    while (send[cur] <= f0) cur++;

    float loc = 0.f;
    #pragma unroll
    for (int i = 0; i < 4; ++i) {
        int f = f0 + i * 256;
        if (f >= send[cur]) {
            atomicAdd(&g_ent[cur], loc); loc = 0.f;
            while (send[cur] <= f) cur++;
        }
        float p = energy[f] * sinv[cur];
        loc += p * __logf(p + EPSF);
    }
    // final flush: warp-aggregate when the whole warp is in one segment
    int first = __shfl_sync(~0u, cur, 0);
    if (__all_sync(~0u, cur == first)) {
        #pragma unroll
        for (int o = 16; o; o >>= 1) loc += __shfl_xor_sync(~0u, loc, o);
        if ((threadIdx.x & 31) == 0) atomicAdd(&g_ent[cur], loc);
    } else {
        atomicAdd(&g_ent[cur], loc);
    }
}

// ---------------------------------------------------------------------------
// Tiny finalizer: one thread per segment computes s_k, conf, mask, type.
__global__ void __launch_bounds__(64) k_epi(const int* __restrict__ segstart,
                                            const int* __restrict__ segend,
                                            const int* __restrict__ etype,
                                            const int* __restrict__ fpsp,
                                            float* __restrict__ out) {
    const int k = threadIdx.x;
    const int s = segstart[k];
    const int e = segend[k];
    const float sumE = g_sumE[k];
    const float len  = (float)(e - s);
    const float inv  = 1.f / len;

    // fps may arrive as int32 or float32: sniff the bit pattern.
    int iv = fpsp[0];
    float fps = (iv >= 1 && iv <= 1000000) ? (float)iv : __int_as_float(iv);

    float sk[8];
    sk[0] = log1pf(len / fps);                      // duration_sec
    sk[1] = log1pf((float)s / fps);                 // latency_sec
    sk[2] = log1pf(sumE * inv);                     // mean_motion
    sk[3] = log1pf(__int_as_float(g_maxE[k]));      // peak_motion
    sk[4] = log1pf(-g_ent[k]);                      // motion_entropy
    sk[5] = log1pf(g_sumSC[k * 3 + 0] * inv);       // vis0
    sk[6] = log1pf(g_sumSC[k * 3 + 1] * inv);       // vis1
    sk[7] = log1pf(g_sumSC[k * 3 + 2] * inv);       // vis2

    float conf = g_sumFC[k] * inv;

    #pragma unroll
    for (int i = 0; i < 8; ++i) {
        g_sk[k * 8 + i] = sk[i];
        out[OUT_SK + k * 8 + i] = sk[i];
    }
    out[OUT_MASK + k] = (conf >= CONF_TH) ? 1.f : 0.f;
    out[OUT_TYPE + k] = (float)etype[k];
    out[OUT_CONF + k] = conf;
}

// ---------------------------------------------------------------------------
// tokens[k][m] = sum_j z[k][j] * W[m][j] + bias[m]; z = [mean_feat | s_k | emb]
__global__ void __launch_bounds__(256) k_gemm(const float* __restrict__ W,
                                              const float* __restrict__ bias,
                                              const float* __restrict__ emb,
                                              const int* __restrict__ etype,
                                              const int* __restrict__ segstart,
                                              const int* __restrict__ segend,
                                              float* __restrict__ out) {
    __shared__ float z[ZDIM];
    const int k = blockIdx.x;
    const float inv = 1.f / (float)(segend[k] - segstart[k]);
    const int ty = etype[k];

    for (int i = threadIdx.x; i < ZDIM; i += 256) {
        float v;
        if (i < DIN)            v = g_esum[k * DIN + i] * inv;
        else if (i < DIN + 8)   v = g_sk[k * 8 + (i - DIN)];
        else                    v = emb[ty * TYPEEMB + (i - DIN - 8)];
        z[i] = v;
    }
    __syncthreads();

    const int w    = threadIdx.x >> 5;
    const int lane = threadIdx.x & 31;
    const int mbase = blockIdx.y * 64 + w * 8;

    #pragma unroll
    for (int r = 0; r < 8; ++r) {
        const int m = mbase + r;
        const float* Wr = W + (size_t)m * ZDIM;
        float acc = 0.f;
        for (int j = lane; j < ZDIM; j += 32) acc += z[j] * Wr[j];
        #pragma unroll
        for (int o = 16; o; o >>= 1) acc += __shfl_xor_sync(~0u, acc, o);
        if (lane == 0) out[OUT_TOKENS + k * DMODEL + m] = acc + bias[m];
    }
}

// ---------------------------------------------------------------------------
extern "C" void kernel_launch(void* const* d_in, const int* in_sizes, int n_in,
                              void* d_out, int out_size) {
    const float* features  = (const float*)d_in[0];   // [T, 512]
    const float* energy    = (const float*)d_in[1];   // [T]
    const float* fconf     = (const float*)d_in[2];   // [T]
    const float* sconf     = (const float*)d_in[3];   // [T, 3]
    const int*   seg_start = (const int*)  d_in[4];   // [64]
    const int*   seg_end   = (const int*)  d_in[5];   // [64]
    const int*   etype     = (const int*)  d_in[6];   // [64]
    const float* emb       = (const float*)d_in[7];   // [16, 32]
    const float* W         = (const float*)d_in[8];   // [256, 552]
    const float* bias      = (const float*)d_in[9];   // [256]
    const int*   fps       = (const int*)  d_in[10];  // scalar
    float* out = (float*)d_out;

    k_zero<<<128, 256>>>();
    k_main<<<1088, 128>>>((const float4*)features, seg_end, energy, fconf, sconf);
    k_ent <<<256, 256>>>(energy, seg_end);
    k_epi <<<1, 64>>>(seg_start, seg_end, etype, fps, out);
    k_gemm<<<dim3(64, 4), 256>>>(W, bias, emb, etype, seg_start, seg_end, out);
}